// round 3
// baseline (speedup 1.0000x reference)
#include <cuda_runtime.h>
#include <cstdint>

#define BB   512      // batch
#define LL   512      // leaves
#define EE   128      // emb
#define OPS  5
#define NI   511      // internal nodes
#define RPC  4        // batch rows per CTA

// scratch: all node embeddings [B][NI][E]  (~134 MB)
__device__ float g_nodes[(size_t)BB * NI * EE];

// ---------------- packed f32x2 helpers ----------------
__device__ __forceinline__ unsigned long long pack2(float lo, float hi) {
    unsigned long long r;
    asm("mov.b64 %0, {%1, %2};" : "=l"(r) : "f"(lo), "f"(hi));
    return r;
}
__device__ __forceinline__ void fma2(unsigned long long& d, unsigned long long a, unsigned long long b) {
    asm("fma.rn.f32x2 %0, %1, %2, %0;" : "+l"(d) : "l"(a), "l"(b));
}
__device__ __forceinline__ unsigned long long add2(unsigned long long a, unsigned long long b) {
    unsigned long long r;
    asm("add.rn.f32x2 %0, %1, %2;" : "=l"(r) : "l"(a), "l"(b));
    return r;
}
__device__ __forceinline__ float2 unpack2(unsigned long long v) {
    float2 f;
    asm("mov.b64 {%0, %1}, %2;" : "=f"(f.x), "=f"(f.y) : "l"(v));
    return f;
}
__device__ __forceinline__ uint32_t smem_u32(const void* p) {
    uint32_t a;
    asm("{ .reg .u64 t; cvta.to.shared.u64 t, %1; cvt.u32.u64 %0, t; }" : "=r"(a) : "l"(p));
    return a;
}
// LDS.128 -> two b64 register pairs (two f32x2 operands = 4 floats)
__device__ __forceinline__ void lds128_pair(unsigned long long& a, unsigned long long& b, uint32_t addr) {
    asm volatile("ld.shared.v2.u64 {%0, %1}, [%2];" : "=l"(a), "=l"(b) : "r"(addr));
}

// ---------------- sequential recurrence ----------------
// 512 threads: h = t&7 (K eighth, interleaved 16B chunks), np = t>>3 (0..63).
// Thread computes output columns nA=np and nB=np+64 (2 cols share each x load).
// Warp lanes h=0..7 fetch 8 consecutive 16B chunks -> one 128B conflict-free
// smem wavefront. Reduction over the 8 K-slices via shuffles (no smem, 1 bar/step).
__global__ void __launch_bounds__(512, 1) recur_kernel(
    const float* __restrict__ emb,   // [B, L, E]
    const float* __restrict__ Ww,    // [2E, E]
    const float* __restrict__ Wb,    // [E]
    const int*   __restrict__ li,    // [NI]
    const int*   __restrict__ ri)    // [NI]
{
    __shared__ __align__(16) float cur[2][RPC][EE];    // double-buffered state
    __shared__ __align__(16) float leafs[2][RPC][EE];  // double-buffered right leaf
    __shared__ int ridx[NI + 1];

    const int t  = threadIdx.x;
    const int h  = t & 7;           // K-slice: chunks k4 = h + 8i, i=0..3
    const int np = t >> 3;          // 0..63
    const int nA = np;
    const int nB = np + 64;
    const int b0 = blockIdx.x * RPC;

    // Weight column slices in registers: 2 sides x 2 cols x 16 K-floats = 32 b64.
    unsigned long long wlA[8], wlB[8], wrA[8], wrB[8];
#pragma unroll
    for (int i = 0; i < 4; i++) {
        const int k0 = (h + 8 * i) * 4;
        wlA[2*i]   = pack2(Ww[(size_t)(k0    ) * EE + nA], Ww[(size_t)(k0 + 1) * EE + nA]);
        wlA[2*i+1] = pack2(Ww[(size_t)(k0 + 2) * EE + nA], Ww[(size_t)(k0 + 3) * EE + nA]);
        wlB[2*i]   = pack2(Ww[(size_t)(k0    ) * EE + nB], Ww[(size_t)(k0 + 1) * EE + nB]);
        wlB[2*i+1] = pack2(Ww[(size_t)(k0 + 2) * EE + nB], Ww[(size_t)(k0 + 3) * EE + nB]);
        wrA[2*i]   = pack2(Ww[(size_t)(EE + k0    ) * EE + nA], Ww[(size_t)(EE + k0 + 1) * EE + nA]);
        wrA[2*i+1] = pack2(Ww[(size_t)(EE + k0 + 2) * EE + nA], Ww[(size_t)(EE + k0 + 3) * EE + nA]);
        wrB[2*i]   = pack2(Ww[(size_t)(EE + k0    ) * EE + nB], Ww[(size_t)(EE + k0 + 1) * EE + nB]);
        wrB[2*i+1] = pack2(Ww[(size_t)(EE + k0 + 2) * EE + nB], Ww[(size_t)(EE + k0 + 3) * EE + nB]);
    }
    const int   ar    = h & 3;                 // row this lane commits
    const int   an    = (h < 4) ? nA : nB;     // column this lane commits
    const float biasv = Wb[an];

    // right-leaf indices into smem
    for (int j = t; j < NI; j += 512) ridx[j] = ri[j];
    if (t == 0) ridx[NI] = ri[0];   // dummy for prefetch overrun

    // init cur[0] = leaf(left_idx[0]); loader mapping: 4 rows x 128 cols
    const int l0   = li[0];
    const int r_ld = t >> 7;
    const int c_ld = t & 127;
    cur[0][r_ld][c_ld] = emb[((size_t)(b0 + r_ld) * LL + l0) * EE + c_ld];
    __syncthreads();

    // prefetch right leaf for step 0
    float lv = emb[((size_t)(b0 + r_ld) * LL + ridx[0]) * EE + c_ld];

    const uint32_t cur_base  = smem_u32(cur);
    const uint32_t leaf_base = smem_u32(leafs);
    const uint32_t hoff = (uint32_t)(h * 16);

    for (int j = 0; j < NI; j++) {
        const int rb = j & 1;           // read state buffer
        const int wb = rb ^ 1;          // write state buffer
        // commit prefetched leaf, then one barrier covers: leaf ready + prev writes
        leafs[rb][r_ld][c_ld] = lv;
        const int rnext = ridx[j + 1];
        __syncthreads();
        lv = emb[((size_t)(b0 + r_ld) * LL + rnext) * EE + c_ld];

#pragma unroll
        for (int r = 0; r < RPC; r++) {
            unsigned long long sA0 = 0ull, sA1 = 0ull, sB0 = 0ull, sB1 = 0ull;
            const uint32_t xl = cur_base  + (uint32_t)(((rb * RPC + r) * EE) * 4) + hoff;
            const uint32_t xr = leaf_base + (uint32_t)(((rb * RPC + r) * EE) * 4) + hoff;
#pragma unroll
            for (int i = 0; i < 4; i++) {
                unsigned long long p0, p1;
                lds128_pair(p0, p1, xl + i * 128);
                fma2(sA0, p0, wlA[2*i]); fma2(sA1, p1, wlA[2*i+1]);
                fma2(sB0, p0, wlB[2*i]); fma2(sB1, p1, wlB[2*i+1]);
            }
#pragma unroll
            for (int i = 0; i < 4; i++) {
                unsigned long long p0, p1;
                lds128_pair(p0, p1, xr + i * 128);
                fma2(sA0, p0, wrA[2*i]); fma2(sA1, p1, wrA[2*i+1]);
                fma2(sB0, p0, wrB[2*i]); fma2(sB1, p1, wrB[2*i+1]);
            }
            // horizontal: 2 packed adds -> 2 scalars
            const float2 fA = unpack2(add2(sA0, sA1));
            const float2 fB = unpack2(add2(sB0, sB1));
            const float vA = fA.x + fA.y;
            const float vB = fB.x + fB.y;
            // cross-half swap-select: lanes h<4 accumulate the A-sum, h>=4 the B-sum
            float u = (h < 4) ? vA : vB;
            u += __shfl_xor_sync(0xFFFFFFFFu, (h < 4) ? vB : vA, 4);
            u += __shfl_xor_sync(0xFFFFFFFFu, u, 1);
            u += __shfl_xor_sync(0xFFFFFFFFu, u, 2);
            if (ar == r) {
                const float v = u + biasv;
                cur[wb][r][an] = v;
                g_nodes[((size_t)(b0 + r) * NI + j) * EE + an] = v;
            }
        }
    }
}

// ---------------- parallel projection: op = node @ G_w + G_b ----------------
// 2 nodes per warp (2 outstanding LDG.128 -> DRAM latency shared)
__global__ void __launch_bounds__(256) proj_kernel(
    const float* __restrict__ Gw,   // [E, OPS]
    const float* __restrict__ Gb,   // [OPS]
    float* __restrict__ out,        // [B, NI, OPS]
    int total_pairs)
{
    __shared__ float gws[EE * OPS];
    __shared__ float gbs[OPS];
    const int t = threadIdx.x;
    for (int i = t; i < EE * OPS; i += blockDim.x) gws[i] = Gw[i];
    if (t < OPS) gbs[t] = Gb[t];
    __syncthreads();

    const int pair = blockIdx.x * (blockDim.x >> 5) + (t >> 5);
    if (pair >= total_pairs) return;
    const int lane  = t & 31;
    const size_t n0 = (size_t)pair * 2;

    const float4 x0 = *(const float4*)&g_nodes[n0 * EE + lane * 4];
    const float4 x1 = *(const float4*)&g_nodes[(n0 + 1) * EE + lane * 4];
    const float* g  = &gws[lane * 4 * OPS];

    float p0[OPS], p1[OPS];
#pragma unroll
    for (int o = 0; o < OPS; o++) {
        p0[o] = x0.x * g[o] + x0.y * g[OPS + o] + x0.z * g[2 * OPS + o] + x0.w * g[3 * OPS + o];
        p1[o] = x1.x * g[o] + x1.y * g[OPS + o] + x1.z * g[2 * OPS + o] + x1.w * g[3 * OPS + o];
    }
#pragma unroll
    for (int off = 16; off; off >>= 1)
#pragma unroll
        for (int o = 0; o < OPS; o++) {
            p0[o] += __shfl_xor_sync(0xFFFFFFFFu, p0[o], off);
            p1[o] += __shfl_xor_sync(0xFFFFFFFFu, p1[o], off);
        }

    if (lane == 0) {
        float* op = out + n0 * OPS;
#pragma unroll
        for (int o = 0; o < OPS; o++) { op[o] = p0[o] + gbs[o]; op[OPS + o] = p1[o] + gbs[o]; }
    }
}

// ---------------- labels tail ----------------
// Labels land on device as int32 (JAX x64 disabled). mode 1: float cast.
// mode 2: widen to raw int64.
__global__ void tail_kernel(const int* __restrict__ labels, float* __restrict__ out, int mode)
{
    const int j = blockIdx.x * blockDim.x + threadIdx.x;
    if (j >= NI) return;
    const size_t base = (size_t)BB * NI * OPS;
    if (mode == 1) {
        out[base + j] = (float)labels[j];
    } else {
        ((long long*)(out + base))[j] = (long long)labels[j];
    }
}

extern "C" void kernel_launch(void* const* d_in, const int* in_sizes, int n_in,
                              void* d_out, int out_size)
{
    const float* emb    = (const float*)d_in[0];
    const float* Ww     = (const float*)d_in[1];
    const float* Wb     = (const float*)d_in[2];
    const float* Gw     = (const float*)d_in[3];
    const float* Gb     = (const float*)d_in[4];
    const int*   li     = (const int*)d_in[5];
    const int*   ri     = (const int*)d_in[6];
    const int*   labels = (const int*)d_in[7];
    float*       out    = (float*)d_out;

    recur_kernel<<<BB / RPC, 512>>>(emb, Ww, Wb, li, ri);

    const int total_pairs = BB * NI / 2;                    // 130816
    proj_kernel<<<total_pairs / 8, 256>>>(Gw, Gb, out, total_pairs); // 8 warps/block

    const long long base = (long long)BB * NI * OPS;
    const long long tail = (long long)out_size - base;
    if (tail == NI)          tail_kernel<<<2, 256>>>(labels, out, 1);
    else if (tail == 2 * NI) tail_kernel<<<2, 256>>>(labels, out, 2);
}

// round 4
// speedup vs baseline: 1.2335x; 1.2335x over previous
#include <cuda_runtime.h>
#include <cstdint>

#define BB   512      // batch
#define LL   512      // leaves
#define EE   128      // emb
#define OPS  5
#define NI   511      // internal nodes
#define RPC  4        // batch rows per CTA

// scratch: all node embeddings [B][NI][E]  (~134 MB)
__device__ float g_nodes[(size_t)BB * NI * EE];

// ---------------- packed f32x2 helpers ----------------
__device__ __forceinline__ unsigned long long pack2(float lo, float hi) {
    unsigned long long r;
    asm("mov.b64 %0, {%1, %2};" : "=l"(r) : "f"(lo), "f"(hi));
    return r;
}
__device__ __forceinline__ void fma2(unsigned long long& d, unsigned long long a, unsigned long long b) {
    asm("fma.rn.f32x2 %0, %1, %2, %0;" : "+l"(d) : "l"(a), "l"(b));
}
__device__ __forceinline__ unsigned long long add2(unsigned long long a, unsigned long long b) {
    unsigned long long r;
    asm("add.rn.f32x2 %0, %1, %2;" : "=l"(r) : "l"(a), "l"(b));
    return r;
}
__device__ __forceinline__ float2 unpack2(unsigned long long v) {
    float2 f;
    asm("mov.b64 {%0, %1}, %2;" : "=f"(f.x), "=f"(f.y) : "l"(v));
    return f;
}
__device__ __forceinline__ uint32_t smem_u32(const void* p) {
    uint32_t a;
    asm("{ .reg .u64 t; cvta.to.shared.u64 t, %1; cvt.u32.u64 %0, t; }" : "=r"(a) : "l"(p));
    return a;
}
// LDS.128 -> two b64 register pairs (two f32x2 operands = 4 floats)
__device__ __forceinline__ void lds128_pair(unsigned long long& a, unsigned long long& b, uint32_t addr) {
    asm volatile("ld.shared.v2.u64 {%0, %1}, [%2];" : "=l"(a), "=l"(b) : "r"(addr));
}
__device__ __forceinline__ unsigned long long shfl_xor64(unsigned long long v, int m) {
    return __shfl_xor_sync(0xFFFFFFFFu, v, m);
}

// ---------------- sequential recurrence ----------------
// 256 threads: h = t&3 (K quarter, interleaved 16B chunks), cg = t>>2 (0..63).
// Thread computes output cols nA=cg, nB=cg+64 (each 16B x-load feeds 4 FFMA2).
// Chunk i of slice h covers floats k = 4h+16i .. +3 (i = 0..7).
// Reduction over the 4 K-slices: 2-stage packed f32x2 shuffle, no 2nd barrier.
__global__ void __launch_bounds__(256, 1) recur_kernel(
    const float* __restrict__ emb,   // [B, L, E]
    const float* __restrict__ Ww,    // [2E, E]
    const float* __restrict__ Wb,    // [E]
    const int*   __restrict__ li,    // [NI]
    const int*   __restrict__ ri)    // [NI]
{
    __shared__ __align__(16) float cur[2][RPC][EE];    // double-buffered state
    __shared__ __align__(16) float leafs[2][RPC][EE];  // double-buffered right leaf
    __shared__ int ridx[NI + 1];

    const int t  = threadIdx.x;
    const int h  = t & 3;           // K-slice
    const int cg = t >> 2;          // 0..63
    const int nA = cg;
    const int nB = cg + 64;
    const int b0 = blockIdx.x * RPC;

    // Weight column slices in registers: 2 sides x 2 cols x 32 K-floats = 64 b64.
    unsigned long long wlA[16], wlB[16], wrA[16], wrB[16];
#pragma unroll
    for (int i = 0; i < 8; i++) {
        const int k0 = 4 * h + 16 * i;
        wlA[2*i]   = pack2(Ww[(size_t)(k0    ) * EE + nA], Ww[(size_t)(k0 + 1) * EE + nA]);
        wlA[2*i+1] = pack2(Ww[(size_t)(k0 + 2) * EE + nA], Ww[(size_t)(k0 + 3) * EE + nA]);
        wlB[2*i]   = pack2(Ww[(size_t)(k0    ) * EE + nB], Ww[(size_t)(k0 + 1) * EE + nB]);
        wlB[2*i+1] = pack2(Ww[(size_t)(k0 + 2) * EE + nB], Ww[(size_t)(k0 + 3) * EE + nB]);
        wrA[2*i]   = pack2(Ww[(size_t)(EE + k0    ) * EE + nA], Ww[(size_t)(EE + k0 + 1) * EE + nA]);
        wrA[2*i+1] = pack2(Ww[(size_t)(EE + k0 + 2) * EE + nA], Ww[(size_t)(EE + k0 + 3) * EE + nA]);
        wrB[2*i]   = pack2(Ww[(size_t)(EE + k0    ) * EE + nB], Ww[(size_t)(EE + k0 + 1) * EE + nB]);
        wrB[2*i+1] = pack2(Ww[(size_t)(EE + k0 + 2) * EE + nB], Ww[(size_t)(EE + k0 + 3) * EE + nB]);
    }
    const unsigned long long bias2 = pack2(Wb[nA], Wb[nB]);

    // right-leaf indices into smem
    for (int j = t; j < NI; j += 256) ridx[j] = ri[j];
    if (t == 0) ridx[NI] = ri[0];   // dummy for prefetch overrun

    // init cur[0] = leaf(left_idx[0]); loader: 4 rows x 64 lanes x float2
    const int l0   = li[0];
    const int r_ld = t >> 6;
    const int c_ld = (t & 63) * 2;
    {
        const float2 v = *(const float2*)&emb[((size_t)(b0 + r_ld) * LL + l0) * EE + c_ld];
        cur[0][r_ld][c_ld]     = v.x;
        cur[0][r_ld][c_ld + 1] = v.y;
    }
    __syncthreads();

    // prefetch right leaf for step 0
    float2 lv = *(const float2*)&emb[((size_t)(b0 + r_ld) * LL + ridx[0]) * EE + c_ld];

    const uint32_t cur_base  = smem_u32(cur);
    const uint32_t leaf_base = smem_u32(leafs);
    const uint32_t hoff = (uint32_t)(h * 16);

    for (int j = 0; j < NI; j++) {
        const int rb = j & 1;           // read state buffer
        const int wb = rb ^ 1;          // write state buffer
        // commit prefetched leaf; one barrier covers leaf-ready + prev cur writes
        leafs[rb][r_ld][c_ld]     = lv.x;
        leafs[rb][r_ld][c_ld + 1] = lv.y;
        const int rnext = ridx[j + 1];
        __syncthreads();
        lv = *(const float2*)&emb[((size_t)(b0 + r_ld) * LL + rnext) * EE + c_ld];

        // ---- phase A: accumulate all rows (independent FMA chains) ----
        unsigned long long accA[RPC], accB[RPC];
#pragma unroll
        for (int r = 0; r < RPC; r++) {
            unsigned long long sA0 = 0ull, sA1 = 0ull, sB0 = 0ull, sB1 = 0ull;
            const uint32_t xl = cur_base  + (uint32_t)(((rb * RPC + r) * EE) * 4) + hoff;
            const uint32_t xr = leaf_base + (uint32_t)(((rb * RPC + r) * EE) * 4) + hoff;
#pragma unroll
            for (int i = 0; i < 8; i++) {
                unsigned long long p0, p1;
                lds128_pair(p0, p1, xl + i * 64);
                fma2(sA0, p0, wlA[2*i]); fma2(sA1, p1, wlA[2*i+1]);
                fma2(sB0, p0, wlB[2*i]); fma2(sB1, p1, wlB[2*i+1]);
            }
#pragma unroll
            for (int i = 0; i < 8; i++) {
                unsigned long long p0, p1;
                lds128_pair(p0, p1, xr + i * 64);
                fma2(sA0, p0, wrA[2*i]); fma2(sA1, p1, wrA[2*i+1]);
                fma2(sB0, p0, wrB[2*i]); fma2(sB1, p1, wrB[2*i+1]);
            }
            accA[r] = add2(sA0, sA1);
            accB[r] = add2(sB0, sB1);
        }

        // ---- phase B: reduce + commit (independent shuffle chains) ----
#pragma unroll
        for (int r = 0; r < RPC; r++) {
            const float2 fA = unpack2(accA[r]);
            const float2 fB = unpack2(accB[r]);
            unsigned long long u = pack2(fA.x + fA.y, fB.x + fB.y);
            u = add2(u, shfl_xor64(u, 1));
            u = add2(u, shfl_xor64(u, 2));      // all 4 h-lanes now hold (yA,yB)
            u = add2(u, bias2);
            if (h == r) {
                const float2 y = unpack2(u);
                cur[wb][r][nA] = y.x;
                cur[wb][r][nB] = y.y;
                float* gn = &g_nodes[((size_t)(b0 + r) * NI + j) * EE];
                gn[nA] = y.x;
                gn[nB] = y.y;
            }
        }
    }
}

// ---------------- parallel projection: op = node @ G_w + G_b ----------------
// 2 nodes per warp (2 outstanding LDG.128 -> DRAM latency shared)
__global__ void __launch_bounds__(256) proj_kernel(
    const float* __restrict__ Gw,   // [E, OPS]
    const float* __restrict__ Gb,   // [OPS]
    float* __restrict__ out,        // [B, NI, OPS]
    int total_pairs)
{
    __shared__ float gws[EE * OPS];
    __shared__ float gbs[OPS];
    const int t = threadIdx.x;
    for (int i = t; i < EE * OPS; i += blockDim.x) gws[i] = Gw[i];
    if (t < OPS) gbs[t] = Gb[t];
    __syncthreads();

    const int pair = blockIdx.x * (blockDim.x >> 5) + (t >> 5);
    if (pair >= total_pairs) return;
    const int lane  = t & 31;
    const size_t n0 = (size_t)pair * 2;

    const float4 x0 = *(const float4*)&g_nodes[n0 * EE + lane * 4];
    const float4 x1 = *(const float4*)&g_nodes[(n0 + 1) * EE + lane * 4];
    const float* g  = &gws[lane * 4 * OPS];

    float p0[OPS], p1[OPS];
#pragma unroll
    for (int o = 0; o < OPS; o++) {
        p0[o] = x0.x * g[o] + x0.y * g[OPS + o] + x0.z * g[2 * OPS + o] + x0.w * g[3 * OPS + o];
        p1[o] = x1.x * g[o] + x1.y * g[OPS + o] + x1.z * g[2 * OPS + o] + x1.w * g[3 * OPS + o];
    }
#pragma unroll
    for (int off = 16; off; off >>= 1)
#pragma unroll
        for (int o = 0; o < OPS; o++) {
            p0[o] += __shfl_xor_sync(0xFFFFFFFFu, p0[o], off);
            p1[o] += __shfl_xor_sync(0xFFFFFFFFu, p1[o], off);
        }

    if (lane == 0) {
        float* op = out + n0 * OPS;
#pragma unroll
        for (int o = 0; o < OPS; o++) { op[o] = p0[o] + gbs[o]; op[OPS + o] = p1[o] + gbs[o]; }
    }
}

// ---------------- labels tail ----------------
// Labels land on device as int32 (JAX x64 disabled). mode 1: float cast.
// mode 2: widen to raw int64.
__global__ void tail_kernel(const int* __restrict__ labels, float* __restrict__ out, int mode)
{
    const int j = blockIdx.x * blockDim.x + threadIdx.x;
    if (j >= NI) return;
    const size_t base = (size_t)BB * NI * OPS;
    if (mode == 1) {
        out[base + j] = (float)labels[j];
    } else {
        ((long long*)(out + base))[j] = (long long)labels[j];
    }
}

extern "C" void kernel_launch(void* const* d_in, const int* in_sizes, int n_in,
                              void* d_out, int out_size)
{
    const float* emb    = (const float*)d_in[0];
    const float* Ww     = (const float*)d_in[1];
    const float* Wb     = (const float*)d_in[2];
    const float* Gw     = (const float*)d_in[3];
    const float* Gb     = (const float*)d_in[4];
    const int*   li     = (const int*)d_in[5];
    const int*   ri     = (const int*)d_in[6];
    const int*   labels = (const int*)d_in[7];
    float*       out    = (float*)d_out;

    recur_kernel<<<BB / RPC, 256>>>(emb, Ww, Wb, li, ri);

    const int total_pairs = BB * NI / 2;                    // 130816
    proj_kernel<<<total_pairs / 8, 256>>>(Gw, Gb, out, total_pairs); // 8 warps/block

    const long long base = (long long)BB * NI * OPS;
    const long long tail = (long long)out_size - base;
    if (tail == NI)          tail_kernel<<<2, 256>>>(labels, out, 1);
    else if (tail == 2 * NI) tail_kernel<<<2, 256>>>(labels, out, 2);
}